// round 14
// baseline (speedup 1.0000x reference)
#include <cuda_runtime.h>
#include <cuda_bf16.h>
#include <math.h>
#include <stdint.h>
#include <stddef.h>

#define V_  16384
#define BV_ 32768
#define C_  256
#define L_  12

// ---------------- packed helpers ----------------
#define FMA2(d, a, b) asm("fma.rn.f32x2 %0, %1, %2, %0;" : "+l"(d) : "l"(a), "l"(b))
__device__ __forceinline__ float2 unpack2(unsigned long long v) {
    float2 r;
    r.x = __uint_as_float((unsigned)(v & 0xffffffffu));
    r.y = __uint_as_float((unsigned)(v >> 32));
    return r;
}
// pack two floats to bf16x2 (lo in low 16 bits)
__device__ __forceinline__ unsigned pack_bf2(float lo, float hi) {
    unsigned d;
    asm("cvt.rn.bf16x2.f32 %0, %1, %2;" : "=r"(d) : "f"(hi), "f"(lo));
    return d;
}
__device__ __forceinline__ float bf_round(float v) {
    return __bfloat162float(__float2bfloat16(v));
}

#define MMA_BF16(c, a0, a1, a2, a3, b0, b1) \
    asm volatile("mma.sync.aligned.m16n8k16.row.col.f32.bf16.bf16.f32 " \
        "{%0,%1,%2,%3}, {%4,%5,%6,%7}, {%8,%9}, {%0,%1,%2,%3};" \
        : "+f"((c)[0]), "+f"((c)[1]), "+f"((c)[2]), "+f"((c)[3]) \
        : "r"(a0), "r"(a1), "r"(a2), "r"(a3), "r"(b0), "r"(b1))

// ---------------- scratch (device globals; no allocations) ----------------
__device__ float g_x [BV_ * C_];
__device__ float g_y [BV_ * C_];
__device__ float g_t [BV_ * C_];
__device__ float g_f0[BV_ * C_];
__device__ float g_f1[BV_ * C_];
__device__ float g_f2[BV_ * C_];
__device__ float g_wt[L_ * C_ * C_];
__device__ unsigned g_wbh[96 * 16 * 256];   // bf16-pair-packed W hi  [kc][kpair][col]
__device__ unsigned g_wbl[96 * 16 * 256];   // bf16-pair-packed W lo
__device__ float g_psum[256 * 256];
__device__ float g_psq [256 * 256];
__device__ float g_sep [128 * 256];
__device__ float g_scale[256];
__device__ float g_shift[256];
__device__ float g_gate[2 * 256];

// ================= weight preprocessing =====================================
// spiral weights w (256, 3072), m = c*12 + t.  k-order: k = t*256 + c.
// output: [kc 0..95][kpair 0..15][col 0..255], each u32 = {bf16(k), bf16(k+1)}
__global__ void transpose_spiral_bf16(const float* __restrict__ w,
                                      unsigned* __restrict__ bh,
                                      unsigned* __restrict__ bl)
{
    int i   = blockIdx.x * 256 + threadIdx.x;   // 393216
    int col = i & 255;
    int kp  = (i >> 8) & 15;
    int kc  = i >> 12;
    int k0  = kc * 32 + kp * 2;
    float v0 = w[col * 3072 + (k0 & 255) * 12 + (k0 >> 8)];
    float v1 = w[col * 3072 + ((k0 + 1) & 255) * 12 + ((k0 + 1) >> 8)];
    float h0 = bf_round(v0), h1 = bf_round(v1);
    bh[i] = pack_bf2(h0, h1);
    bl[i] = pack_bf2(v0 - h0, v1 - h1);
}

// dense weights: w (N, K) -> wt[k*N + o]
__global__ void transpose_dense(const float* __restrict__ w, float* __restrict__ wt,
                                int N, int K)
{
    int i = blockIdx.x * 256 + threadIdx.x;
    if (i >= N * K) return;
    int o = i % N;
    int k = i / N;
    wt[i] = w[o * K + k];
}

// ================= spiral conv GEMM via mma.sync bf16x3 =====================
// y[bv][n] = bias[n] + sum_k A[bv][k] * W[k][n],  A[bv][k] = x[bV + J[t,bv]][c]
// CTA: 128 M x 128 N (grid = 256 Mblocks x 2 Nhalves). 8 warps of 32x64.
__global__ __launch_bounds__(256, 2)
void spiral_gemm_mma(const float* __restrict__ x, const int* __restrict__ idxp,
                     const unsigned* __restrict__ wbh, const unsigned* __restrict__ wbl,
                     const float* __restrict__ bias, float* __restrict__ y)
{
    __shared__ unsigned Ah[128 * 20];
    __shared__ unsigned Al[128 * 20];
    __shared__ unsigned Bh[16 * 136];
    __shared__ unsigned Bl[16 * 136];
    __shared__ int      Js[12 * 128];

    const int tid   = threadIdx.x;
    const int wid   = tid >> 5;
    const int lane  = tid & 31;
    const int lane4 = lane >> 2;     // group id (0..7)
    const int lanek = lane & 3;
    const int mb    = blockIdx.x >> 1;
    const int nhalf = blockIdx.x & 1;
    const int row0  = mb << 7;
    const int b     = row0 >> 14;
    const int u0    = row0 & (V_ - 1);
    const int baseB = b * V_;
    const int warpM = wid & 3;
    const int warpN = wid >> 2;

    for (int i = tid; i < 12 * 128; i += 256)
        Js[i] = idxp[(i >> 7) * V_ + u0 + (i & 127)];

    float acc[2][8][4];
#pragma unroll
    for (int mi = 0; mi < 2; mi++)
#pragma unroll
        for (int ni = 0; ni < 8; ni++)
#pragma unroll
            for (int j = 0; j < 4; j++) acc[mi][ni][j] = 0.f;

    const int arow = warpM * 32 + lane4;

    for (int kc = 0; kc < 96; kc++) {
        const int t  = kc >> 3;
        const int c0 = (kc & 7) << 5;
        __syncthreads();
        // ---- A tile: gather 128 rows x 32 ch, split hi/lo, pack bf16 pairs ----
#pragma unroll
        for (int p = 0; p < 4; p++) {
            int f    = tid + (p << 8);       // 0..1023
            int row  = f >> 3;
            int slot = f & 7;                // 4 floats = 2 kpairs
            const float4 v = *reinterpret_cast<const float4*>(
                x + (size_t)(baseB + Js[(t << 7) + row]) * 256 + c0 + (slot << 2));
            float hx = bf_round(v.x), hy = bf_round(v.y);
            float hz = bf_round(v.z), hw = bf_round(v.w);
            uint2 hi = make_uint2(pack_bf2(hx, hy), pack_bf2(hz, hw));
            uint2 lo = make_uint2(pack_bf2(v.x - hx, v.y - hy),
                                  pack_bf2(v.z - hz, v.w - hw));
            *reinterpret_cast<uint2*>(&Ah[row * 20 + slot * 2]) = hi;
            *reinterpret_cast<uint2*>(&Al[row * 20 + slot * 2]) = lo;
        }
        // ---- B tiles: copy pre-packed weights (this CTA's 128-col half) ----
#pragma unroll
        for (int p = 0; p < 4; p++) {
            int f     = tid + (p << 8);      // 0..1023 uint4s
            int split = f >> 9;
            int kp    = (f >> 5) & 15;
            int c4    = (f & 31) << 2;
            const unsigned* src = (split ? wbl : wbh)
                + ((size_t)(kc * 16 + kp) << 8) + (nhalf << 7) + c4;
            unsigned* dst = (split ? Bl : Bh) + kp * 136 + c4;
            *reinterpret_cast<uint4*>(dst) = *reinterpret_cast<const uint4*>(src);
        }
        __syncthreads();

#pragma unroll
        for (int ks = 0; ks < 2; ks++) {
            const int kp0 = ks << 3;
            unsigned ah[2][4], al[2][4], bb[8][2];
#pragma unroll
            for (int mi = 0; mi < 2; mi++) {
                int base = (arow + mi * 16) * 20 + kp0 + lanek;
                ah[mi][0] = Ah[base];       ah[mi][1] = Ah[base + 160];
                ah[mi][2] = Ah[base + 4];   ah[mi][3] = Ah[base + 164];
            }
#pragma unroll
            for (int ni = 0; ni < 8; ni++) {
                int bcol = warpN * 64 + ni * 8 + lane4;
                bb[ni][0] = Bh[(kp0 + lanek) * 136 + bcol];
                bb[ni][1] = Bh[(kp0 + 4 + lanek) * 136 + bcol];
            }
#pragma unroll
            for (int mi = 0; mi < 2; mi++)
#pragma unroll
                for (int ni = 0; ni < 8; ni++)
                    MMA_BF16(acc[mi][ni], ah[mi][0], ah[mi][1], ah[mi][2], ah[mi][3],
                             bb[ni][0], bb[ni][1]);
            // al x bh
#pragma unroll
            for (int mi = 0; mi < 2; mi++) {
                int base = (arow + mi * 16) * 20 + kp0 + lanek;
                al[mi][0] = Al[base];       al[mi][1] = Al[base + 160];
                al[mi][2] = Al[base + 4];   al[mi][3] = Al[base + 164];
            }
#pragma unroll
            for (int mi = 0; mi < 2; mi++)
#pragma unroll
                for (int ni = 0; ni < 8; ni++)
                    MMA_BF16(acc[mi][ni], al[mi][0], al[mi][1], al[mi][2], al[mi][3],
                             bb[ni][0], bb[ni][1]);
            // ah x bl (overwrite bb with lo weights)
#pragma unroll
            for (int ni = 0; ni < 8; ni++) {
                int bcol = warpN * 64 + ni * 8 + lane4;
                bb[ni][0] = Bl[(kp0 + lanek) * 136 + bcol];
                bb[ni][1] = Bl[(kp0 + 4 + lanek) * 136 + bcol];
            }
#pragma unroll
            for (int mi = 0; mi < 2; mi++)
#pragma unroll
                for (int ni = 0; ni < 8; ni++)
                    MMA_BF16(acc[mi][ni], ah[mi][0], ah[mi][1], ah[mi][2], ah[mi][3],
                             bb[ni][0], bb[ni][1]);
        }
    }

    // ---- epilogue: add bias, store ----
#pragma unroll
    for (int mi = 0; mi < 2; mi++) {
        int row = row0 + warpM * 32 + mi * 16 + lane4;
#pragma unroll
        for (int ni = 0; ni < 8; ni++) {
            int col = (nhalf << 7) + warpN * 64 + ni * 8 + lanek * 2;
            float2 bb2 = *reinterpret_cast<const float2*>(bias + col);
            float* d0 = y + (size_t)row * 256 + col;
            float* d1 = y + (size_t)(row + 8) * 256 + col;
            *reinterpret_cast<float2*>(d0) =
                make_float2(acc[mi][ni][0] + bb2.x, acc[mi][ni][1] + bb2.y);
            *reinterpret_cast<float2*>(d1) =
                make_float2(acc[mi][ni][2] + bb2.x, acc[mi][ni][3] + bb2.y);
        }
    }
}

// ================= dense GEMM (skip conv / classifier), FFMA2 core ==========
template <int N, int K, bool CONCAT>
__global__ __launch_bounds__(256, 2)
void dense_gemm(const float* __restrict__ a0, const float* __restrict__ a1,
                const float* __restrict__ wt, const float* __restrict__ bias,
                float* __restrict__ y)
{
    constexpr int TO = N / 32;
    constexpr int PT = TO / 2;
    __shared__ float2 Ash[64][19];
    __shared__ float  Wsh[16][N + 4];
    const int tid  = threadIdx.x;
    const int warp = tid >> 5;
    const int lane = tid & 31;
    const int row0 = blockIdx.x << 6;

    unsigned long long acc[8][PT];
#pragma unroll
    for (int i = 0; i < 8; i++)
#pragma unroll
        for (int j = 0; j < PT; j++) acc[i][j] = 0ull;

    const int gv  = tid >> 2;
    const int gc4 = (tid & 3) << 2;

    for (int k0 = 0; k0 < K; k0 += 16) {
        __syncthreads();
        const float* src;
        int koff, KS;
        if (CONCAT) {
            if (k0 < 256) { src = a0; koff = k0; }
            else          { src = a1; koff = k0 - 256; }
            KS = 256;
        } else {
            src = a0; koff = k0; KS = K;
        }
        {
            const float4 v = *reinterpret_cast<const float4*>(
                src + (size_t)(row0 + gv) * KS + koff + gc4);
            Ash[gv][gc4 + 0] = make_float2(v.x, v.x);
            Ash[gv][gc4 + 1] = make_float2(v.y, v.y);
            Ash[gv][gc4 + 2] = make_float2(v.z, v.z);
            Ash[gv][gc4 + 3] = make_float2(v.w, v.w);
        }
        {
            const float* wsrc = wt + (size_t)k0 * N;
            constexpr int NF4 = 16 * N / 4;
#pragma unroll
            for (int i = tid; i < NF4; i += 256) {
                int r  = i / (N / 4);
                int cc = (i % (N / 4)) << 2;
                *reinterpret_cast<float4*>(&Wsh[r][cc]) =
                    *reinterpret_cast<const float4*>(wsrc + r * N + cc);
            }
        }
        __syncthreads();
#pragma unroll
        for (int kk = 0; kk < 16; kk++) {
            unsigned long long a2[8];
#pragma unroll
            for (int i = 0; i < 8; i++)
                a2[i] = *reinterpret_cast<const unsigned long long*>(
                            &Ash[(warp << 3) + i][kk]);
            unsigned long long w2[PT];
            if (PT == 4) {
                ulonglong2 wA = *reinterpret_cast<const ulonglong2*>(&Wsh[kk][lane * 8]);
                ulonglong2 wB = *reinterpret_cast<const ulonglong2*>(&Wsh[kk][lane * 8 + 4]);
                w2[0] = wA.x; w2[1] = wA.y; w2[2] = wB.x; w2[3] = wB.y;
            } else if (PT == 2) {
                ulonglong2 wA = *reinterpret_cast<const ulonglong2*>(&Wsh[kk][lane * 4]);
                w2[0] = wA.x; w2[1] = wA.y;
            } else {
                w2[0] = *reinterpret_cast<const unsigned long long*>(&Wsh[kk][lane * 2]);
            }
#pragma unroll
            for (int i = 0; i < 8; i++)
#pragma unroll
                for (int j = 0; j < PT; j++)
                    FMA2(acc[i][j], a2[i], w2[j]);
        }
    }

    float bv[TO];
#pragma unroll
    for (int j = 0; j < TO; j++) bv[j] = bias[lane * TO + j];
#pragma unroll
    for (int i = 0; i < 8; i++) {
        int row = row0 + (warp << 3) + i;
#pragma unroll
        for (int j = 0; j < PT; j++) {
            float2 p = unpack2(acc[i][j]);
            y[(size_t)row * N + lane * TO + 2 * j]     = p.x + bv[2 * j];
            y[(size_t)row * N + lane * TO + 2 * j + 1] = p.y + bv[2 * j + 1];
        }
    }
}

// ---------------- encoder block 0 conv (C_in = 3, K = 36) ----------------
__global__ __launch_bounds__(256)
void enc0_conv(const float* __restrict__ verts, const int* __restrict__ idxp,
               const float* __restrict__ wt /*[m][o]*/, const float* __restrict__ bias,
               float* __restrict__ y)
{
    __shared__ float Wsh[36][256];
    __shared__ float A[8][36];
    __shared__ int   Js[12][128];
    const int tid  = threadIdx.x;
    const int row0 = blockIdx.x * 128;
    const int b    = row0 >> 14;
    const int u0   = row0 & (V_ - 1);
    const int baseB = b * V_;

    for (int i = tid; i < 36 * 256; i += 256) Wsh[i >> 8][i & 255] = wt[i];
    for (int i = tid; i < 12 * 128; i += 256) {
        int t = i >> 7, uu = i & 127;
        Js[t][uu] = idxp[t * V_ + u0 + uu];
    }
    const float bval = bias[tid];

    for (int g = 0; g < 16; g++) {
        __syncthreads();
        for (int i = tid; i < 8 * 36; i += 256) {
            int vv = i / 36, m = i % 36;
            int c = m / 12, t = m % 12;
            A[vv][m] = verts[(size_t)(baseB + Js[t][g * 8 + vv]) * 3 + c];
        }
        __syncthreads();
        float s[8];
#pragma unroll
        for (int v = 0; v < 8; v++) s[v] = bval;
#pragma unroll
        for (int m = 0; m < 36; m++) {
            float wm = Wsh[m][tid];
#pragma unroll
            for (int v = 0; v < 8; v++) s[v] = fmaf(wm, A[v][m], s[v]);
        }
#pragma unroll
        for (int v = 0; v < 8; v++)
            y[(size_t)(row0 + g * 8 + v) * 256 + tid] = s[v];
    }
}

// ---------------- BN stats (deterministic two-level reduction) ----------------
__global__ void stats_partial(const float* __restrict__ y, int C,
                              float* __restrict__ psum, float* __restrict__ psq)
{
    int tid = threadIdx.x;
    int r0  = blockIdx.x * 128;
    float s = 0.f, q = 0.f;
    for (int r = 0; r < 128; r++) {
        float v = y[(size_t)(r0 + r) * C + tid];
        s += v;
        q += v * v;
    }
    psum[blockIdx.x * C + tid] = s;
    psq [blockIdx.x * C + tid] = q;
}

__global__ void bn_finalize(const float* __restrict__ psum, const float* __restrict__ psq,
                            const float* __restrict__ g, const float* __restrict__ beta,
                            int C, float* __restrict__ scale, float* __restrict__ shift)
{
    __shared__ float ss[256];
    __shared__ float qq[256];
    int c = blockIdx.x;
    int i = threadIdx.x;
    ss[i] = psum[i * C + c];
    qq[i] = psq [i * C + c];
    __syncthreads();
#pragma unroll
    for (int s = 128; s > 0; s >>= 1) {
        if (i < s) { ss[i] += ss[i + s]; qq[i] += qq[i + s]; }
        __syncthreads();
    }
    if (i == 0) {
        float mean = ss[0] * (1.f / 32768.f);
        float var  = qq[0] * (1.f / 32768.f) - mean * mean;
        float sc   = g[c] * rsqrtf(var + 1e-5f);
        scale[c] = sc;
        shift[c] = beta[c] - mean * sc;
    }
}

__global__ void bn_apply(const float4* __restrict__ y, const float4* __restrict__ res,
                         float4* __restrict__ out, const float* __restrict__ scale,
                         const float* __restrict__ shift, int C4)
{
    int i  = blockIdx.x * 256 + threadIdx.x;
    int c4 = i & (C4 - 1);
    float4 sc = reinterpret_cast<const float4*>(scale)[c4];
    float4 sh = reinterpret_cast<const float4*>(shift)[c4];
    float4 v  = y[i];
    float4 r;
    r.x = fmaxf(fmaf(v.x, sc.x, sh.x), 0.f);
    r.y = fmaxf(fmaf(v.y, sc.y, sh.y), 0.f);
    r.z = fmaxf(fmaf(v.z, sc.z, sh.z), 0.f);
    r.w = fmaxf(fmaf(v.w, sc.w, sh.w), 0.f);
    if (res) {
        float4 rr = res[i];
        r.x += rr.x; r.y += rr.y; r.z += rr.z; r.w += rr.w;
    }
    out[i] = r;
}

// ---------------- SE ----------------
__global__ void se_partial(const float* __restrict__ z, float* __restrict__ sep)
{
    int tid = threadIdx.x;
    int r0  = blockIdx.x * 256;
    float s = 0.f;
    for (int r = 0; r < 256; r++) s += z[(size_t)(r0 + r) * 256 + tid];
    sep[blockIdx.x * 256 + tid] = s;
}

__global__ void se_gate(const float* __restrict__ sep, const float* __restrict__ w1,
                        const float* __restrict__ w2, float* __restrict__ gate)
{
    int tid = threadIdx.x;
    __shared__ float ss[256];
    __shared__ float hh[32];
    for (int b = 0; b < 2; b++) {
        float s = 0.f;
        for (int i = 0; i < 64; i++) s += sep[(b * 64 + i) * 256 + tid];
        ss[tid] = s * (1.f / 16384.f);
        __syncthreads();
        if (tid < 32) {
            float h = 0.f;
            for (int c = 0; c < 256; c++) h = fmaf(w1[tid * 256 + c], ss[c], h);
            hh[tid] = fmaxf(h, 0.f);
        }
        __syncthreads();
        float gs = 0.f;
#pragma unroll
        for (int r = 0; r < 32; r++) gs = fmaf(w2[tid * 32 + r], hh[r], gs);
        gate[b * 256 + tid] = 1.f / (1.f + expf(-gs));
        __syncthreads();
    }
}

__global__ void se_apply(const float4* __restrict__ z, const float* __restrict__ gate,
                         float4* __restrict__ out0, float4* __restrict__ out1)
{
    int i  = blockIdx.x * 256 + threadIdx.x;
    int c4 = i & 63;
    int b  = i >> 20;
    float4 g = reinterpret_cast<const float4*>(gate)[(b << 6) + c4];
    float4 v = z[i];
    float4 r = make_float4(v.x * g.x, v.y * g.y, v.z * g.z, v.w * g.w);
    out0[i] = r;
    if (out1) out1[i] = r;
}

// ---------------- classifier final 1x64 ----------------
__global__ void cls3_kernel(const float* __restrict__ h, const float* __restrict__ w,
                            const float* __restrict__ b, float* __restrict__ out)
{
    __shared__ float ws[64];
    int tid = threadIdx.x;
    if (tid < 64) ws[tid] = w[tid];
    __syncthreads();
    int bv = blockIdx.x * 256 + tid;
    const float4* hp = reinterpret_cast<const float4*>(h + (size_t)bv * 64);
    float s = __ldg(b);
#pragma unroll
    for (int i = 0; i < 16; i++) {
        float4 v = hp[i];
        s = fmaf(v.x, ws[i * 4 + 0], s);
        s = fmaf(v.y, ws[i * 4 + 1], s);
        s = fmaf(v.z, ws[i * 4 + 2], s);
        s = fmaf(v.w, ws[i * 4 + 3], s);
    }
    out[bv] = s;
}

// ---------------- host orchestration ----------------
extern "C" void kernel_launch(void* const* d_in, const int* in_sizes, int n_in,
                              void* d_out, int out_size)
{
    const float* verts   = (const float*)d_in[0];
    const int*   spirals = (const int*)  d_in[1];
    const float* enc0_w  = (const float*)d_in[2];
    const float* enc0_b  = (const float*)d_in[3];
    const float* enc0_g  = (const float*)d_in[4];
    const float* enc0_be = (const float*)d_in[5];
    const float* enc_w   = (const float*)d_in[6];
    const float* enc_b   = (const float*)d_in[7];
    const float* enc_g   = (const float*)d_in[8];
    const float* enc_be  = (const float*)d_in[9];
    const float* se_w1   = (const float*)d_in[10];
    const float* se_w2   = (const float*)d_in[11];
    const float* skip_w  = (const float*)d_in[12];
    const float* skip_b  = (const float*)d_in[13];
    const float* dec_w   = (const float*)d_in[14];
    const float* dec_b   = (const float*)d_in[15];
    const float* dec_g   = (const float*)d_in[16];
    const float* dec_be  = (const float*)d_in[17];
    const float* cls1_w  = (const float*)d_in[18];
    const float* cls1_b  = (const float*)d_in[19];
    const float* cls1_g  = (const float*)d_in[20];
    const float* cls1_be = (const float*)d_in[21];
    const float* cls2_w  = (const float*)d_in[22];
    const float* cls2_b  = (const float*)d_in[23];
    const float* cls2_g  = (const float*)d_in[24];
    const float* cls2_be = (const float*)d_in[25];
    const float* cls3_w  = (const float*)d_in[26];
    const float* cls3_b  = (const float*)d_in[27];
    float* outp = (float*)d_out;
    (void)in_sizes; (void)n_in; (void)out_size;

    float *px, *py, *pt, *pwt, *pps, *ppq, *psep, *psc, *psh, *pg;
    unsigned *pwbh, *pwbl;
    float *pf[3];
    cudaGetSymbolAddress((void**)&px,    g_x);
    cudaGetSymbolAddress((void**)&py,    g_y);
    cudaGetSymbolAddress((void**)&pt,    g_t);
    cudaGetSymbolAddress((void**)&pf[0], g_f0);
    cudaGetSymbolAddress((void**)&pf[1], g_f1);
    cudaGetSymbolAddress((void**)&pf[2], g_f2);
    cudaGetSymbolAddress((void**)&pwt,   g_wt);
    cudaGetSymbolAddress((void**)&pwbh,  g_wbh);
    cudaGetSymbolAddress((void**)&pwbl,  g_wbl);
    cudaGetSymbolAddress((void**)&pps,   g_psum);
    cudaGetSymbolAddress((void**)&ppq,   g_psq);
    cudaGetSymbolAddress((void**)&psep,  g_sep);
    cudaGetSymbolAddress((void**)&psc,   g_scale);
    cudaGetSymbolAddress((void**)&psh,   g_shift);
    cudaGetSymbolAddress((void**)&pg,    g_gate);

    // ---------- encoder block 0 ----------
    transpose_dense<<<(256 * 36 + 255) / 256, 256>>>(enc0_w, pwt, 256, 36);
    enc0_conv<<<256, 256>>>(verts, spirals, pwt, enc0_b, py);
    stats_partial<<<256, 256>>>(py, 256, pps, ppq);
    bn_finalize<<<256, 256>>>(pps, ppq, enc0_g, enc0_be, 256, psc, psh);
    bn_apply<<<8192, 256>>>((const float4*)py, nullptr, (float4*)pt, psc, psh, 64);
    se_partial<<<128, 256>>>(pt, psep);
    se_gate<<<1, 256>>>(psep, se_w1, se_w2, pg);
    se_apply<<<8192, 256>>>((const float4*)pt, pg, (float4*)px, (float4*)pf[0]);

    // ---------- encoder blocks 1..3 ----------
    for (int i = 1; i < 4; i++) {
        transpose_spiral_bf16<<<1536, 256>>>(enc_w + (size_t)(i - 1) * 786432, pwbh, pwbl);
        spiral_gemm_mma<<<512, 256>>>(px, spirals + i * (V_ * L_), pwbh, pwbl,
                                      enc_b + (i - 1) * 256, py);
        stats_partial<<<256, 256>>>(py, 256, pps, ppq);
        bn_finalize<<<256, 256>>>(pps, ppq, enc_g + (i - 1) * 256, enc_be + (i - 1) * 256,
                                  256, psc, psh);
        bn_apply<<<8192, 256>>>((const float4*)py, (const float4*)px, (float4*)pt,
                                psc, psh, 64);
        se_partial<<<128, 256>>>(pt, psep);
        se_gate<<<1, 256>>>(psep, se_w1 + i * 8192, se_w2 + i * 8192, pg);
        se_apply<<<8192, 256>>>((const float4*)pt, pg, (float4*)px,
                                (i < 3) ? (float4*)pf[i] : nullptr);
    }

    // ---------- decoder ----------
    for (int i = 0; i < 3; i++) {
        transpose_dense<<<(512 * 256 + 255) / 256, 256>>>(skip_w + (size_t)i * 131072,
                                                          pwt, 256, 512);
        dense_gemm<256, 512, true><<<512, 256>>>(px, pf[2 - i], pwt,
                                                 skip_b + i * 256, pt);
        transpose_spiral_bf16<<<1536, 256>>>(dec_w + (size_t)i * 786432, pwbh, pwbl);
        spiral_gemm_mma<<<512, 256>>>(pt, spirals + (2 - i) * (V_ * L_), pwbh, pwbl,
                                      dec_b + i * 256, py);
        stats_partial<<<256, 256>>>(py, 256, pps, ppq);
        bn_finalize<<<256, 256>>>(pps, ppq, dec_g + i * 256, dec_be + i * 256,
                                  256, psc, psh);
        bn_apply<<<8192, 256>>>((const float4*)py, (const float4*)pt, (float4*)px,
                                psc, psh, 64);
    }

    // ---------- classifier ----------
    transpose_dense<<<(128 * 256 + 255) / 256, 256>>>(cls1_w, pwt, 128, 256);
    dense_gemm<128, 256, false><<<512, 256>>>(px, nullptr, pwt, cls1_b, py);
    stats_partial<<<256, 128>>>(py, 128, pps, ppq);
    bn_finalize<<<128, 256>>>(pps, ppq, cls1_g, cls1_be, 128, psc, psh);
    bn_apply<<<4096, 256>>>((const float4*)py, nullptr, (float4*)pt, psc, psh, 32);

    transpose_dense<<<(64 * 128 + 255) / 256, 256>>>(cls2_w, pwt, 64, 128);
    dense_gemm<64, 128, false><<<512, 256>>>(pt, nullptr, pwt, cls2_b, py);
    stats_partial<<<256, 64>>>(py, 64, pps, ppq);
    bn_finalize<<<64, 256>>>(pps, ppq, cls2_g, cls2_be, 64, psc, psh);
    bn_apply<<<2048, 256>>>((const float4*)py, nullptr, (float4*)pt, psc, psh, 16);

    cls3_kernel<<<128, 256>>>(pt, cls3_w, cls3_b, outp);
}

// round 15
// speedup vs baseline: 1.0004x; 1.0004x over previous
#include <cuda_runtime.h>
#include <cuda_bf16.h>
#include <math.h>
#include <stdint.h>
#include <stddef.h>

#define V_  16384
#define BV_ 32768
#define C_  256
#define L_  12

// ---------------- packed helpers ----------------
#define FMA2(d, a, b) asm("fma.rn.f32x2 %0, %1, %2, %0;" : "+l"(d) : "l"(a), "l"(b))
__device__ __forceinline__ float2 unpack2(unsigned long long v) {
    float2 r;
    r.x = __uint_as_float((unsigned)(v & 0xffffffffu));
    r.y = __uint_as_float((unsigned)(v >> 32));
    return r;
}
// pack two floats to bf16x2 (lo in low 16 bits)
__device__ __forceinline__ unsigned pack_bf2(float lo, float hi) {
    unsigned d;
    asm("cvt.rn.bf16x2.f32 %0, %1, %2;" : "=r"(d) : "f"(hi), "f"(lo));
    return d;
}
__device__ __forceinline__ float bf_round(float v) {
    return __bfloat162float(__float2bfloat16(v));
}

#define MMA_BF16(c, a0, a1, a2, a3, b0, b1) \
    asm volatile("mma.sync.aligned.m16n8k16.row.col.f32.bf16.bf16.f32 " \
        "{%0,%1,%2,%3}, {%4,%5,%6,%7}, {%8,%9}, {%0,%1,%2,%3};" \
        : "+f"((c)[0]), "+f"((c)[1]), "+f"((c)[2]), "+f"((c)[3]) \
        : "r"(a0), "r"(a1), "r"(a2), "r"(a3), "r"(b0), "r"(b1))

// ---------------- scratch (device globals; no allocations) ----------------
__device__ float g_x [BV_ * C_];
__device__ float g_y [BV_ * C_];
__device__ float g_t [BV_ * C_];
__device__ float g_f0[BV_ * C_];
__device__ float g_f1[BV_ * C_];
__device__ float g_f2[BV_ * C_];
__device__ float g_wt[L_ * C_ * C_];
__device__ unsigned g_wbh[96 * 16 * 256];   // bf16-pair-packed W hi  [kc][kpair][col]
__device__ unsigned g_wbl[96 * 16 * 256];   // bf16-pair-packed W lo
__device__ float g_psum[256 * 256];
__device__ float g_psq [256 * 256];
__device__ float g_sep [128 * 256];
__device__ float g_scale[256];
__device__ float g_shift[256];
__device__ float g_gate[2 * 256];

// ================= weight preprocessing =====================================
// spiral weights w (256, 3072), m = c*12 + t.  k-order: k = t*256 + c.
// output: [kc 0..95][kpair 0..15][col 0..255], each u32 = {bf16(k), bf16(k+1)}
__global__ void transpose_spiral_bf16(const float* __restrict__ w,
                                      unsigned* __restrict__ bh,
                                      unsigned* __restrict__ bl)
{
    int i   = blockIdx.x * 256 + threadIdx.x;   // 393216
    int col = i & 255;
    int kp  = (i >> 8) & 15;
    int kc  = i >> 12;
    int k0  = kc * 32 + kp * 2;
    float v0 = w[col * 3072 + (k0 & 255) * 12 + (k0 >> 8)];
    float v1 = w[col * 3072 + ((k0 + 1) & 255) * 12 + ((k0 + 1) >> 8)];
    float h0 = bf_round(v0), h1 = bf_round(v1);
    bh[i] = pack_bf2(h0, h1);
    bl[i] = pack_bf2(v0 - h0, v1 - h1);
}

// dense weights: w (N, K) -> wt[k*N + o]
__global__ void transpose_dense(const float* __restrict__ w, float* __restrict__ wt,
                                int N, int K)
{
    int i = blockIdx.x * 256 + threadIdx.x;
    if (i >= N * K) return;
    int o = i % N;
    int k = i / N;
    wt[i] = w[o * K + k];
}

// ================= spiral conv GEMM via mma.sync bf16x3 =====================
// y[bv][n] = bias[n] + sum_k A[bv][k] * W[k][n],  A[bv][k] = x[bV + J[t,bv]][c]
// CTA: 128 M x 128 N (grid = 256 Mblocks x 2 Nhalves). 8 warps of 32x64.
__global__ __launch_bounds__(256, 2)
void spiral_gemm_mma(const float* __restrict__ x, const int* __restrict__ idxp,
                     const unsigned* __restrict__ wbh, const unsigned* __restrict__ wbl,
                     const float* __restrict__ bias, float* __restrict__ y)
{
    __shared__ unsigned Ah[128 * 20];
    __shared__ unsigned Al[128 * 20];
    __shared__ unsigned Bh[16 * 136];
    __shared__ unsigned Bl[16 * 136];
    __shared__ int      Js[12 * 128];

    const int tid   = threadIdx.x;
    const int wid   = tid >> 5;
    const int lane  = tid & 31;
    const int lane4 = lane >> 2;     // group id (0..7)
    const int lanek = lane & 3;
    const int mb    = blockIdx.x >> 1;
    const int nhalf = blockIdx.x & 1;
    const int row0  = mb << 7;
    const int b     = row0 >> 14;
    const int u0    = row0 & (V_ - 1);
    const int baseB = b * V_;
    const int warpM = wid & 3;
    const int warpN = wid >> 2;

    for (int i = tid; i < 12 * 128; i += 256)
        Js[i] = idxp[(i >> 7) * V_ + u0 + (i & 127)];

    float acc[2][8][4];
#pragma unroll
    for (int mi = 0; mi < 2; mi++)
#pragma unroll
        for (int ni = 0; ni < 8; ni++)
#pragma unroll
            for (int j = 0; j < 4; j++) acc[mi][ni][j] = 0.f;

    const int arow = warpM * 32 + lane4;

    for (int kc = 0; kc < 96; kc++) {
        const int t  = kc >> 3;
        const int c0 = (kc & 7) << 5;
        __syncthreads();
        // ---- A tile: gather 128 rows x 32 ch, split hi/lo, pack bf16 pairs ----
#pragma unroll
        for (int p = 0; p < 4; p++) {
            int f    = tid + (p << 8);       // 0..1023
            int row  = f >> 3;
            int slot = f & 7;                // 4 floats = 2 kpairs
            const float4 v = *reinterpret_cast<const float4*>(
                x + (size_t)(baseB + Js[(t << 7) + row]) * 256 + c0 + (slot << 2));
            float hx = bf_round(v.x), hy = bf_round(v.y);
            float hz = bf_round(v.z), hw = bf_round(v.w);
            uint2 hi = make_uint2(pack_bf2(hx, hy), pack_bf2(hz, hw));
            uint2 lo = make_uint2(pack_bf2(v.x - hx, v.y - hy),
                                  pack_bf2(v.z - hz, v.w - hw));
            *reinterpret_cast<uint2*>(&Ah[row * 20 + slot * 2]) = hi;
            *reinterpret_cast<uint2*>(&Al[row * 20 + slot * 2]) = lo;
        }
        // ---- B tiles: copy pre-packed weights (this CTA's 128-col half) ----
#pragma unroll
        for (int p = 0; p < 4; p++) {
            int f     = tid + (p << 8);      // 0..1023 uint4s
            int split = f >> 9;
            int kp    = (f >> 5) & 15;
            int c4    = (f & 31) << 2;
            const unsigned* src = (split ? wbl : wbh)
                + ((size_t)(kc * 16 + kp) << 8) + (nhalf << 7) + c4;
            unsigned* dst = (split ? Bl : Bh) + kp * 136 + c4;
            *reinterpret_cast<uint4*>(dst) = *reinterpret_cast<const uint4*>(src);
        }
        __syncthreads();

#pragma unroll
        for (int ks = 0; ks < 2; ks++) {
            const int kp0 = ks << 3;
            unsigned ah[2][4], al[2][4], bb[8][2];
#pragma unroll
            for (int mi = 0; mi < 2; mi++) {
                int base = (arow + mi * 16) * 20 + kp0 + lanek;
                ah[mi][0] = Ah[base];       ah[mi][1] = Ah[base + 160];
                ah[mi][2] = Ah[base + 4];   ah[mi][3] = Ah[base + 164];
            }
#pragma unroll
            for (int ni = 0; ni < 8; ni++) {
                int bcol = warpN * 64 + ni * 8 + lane4;
                bb[ni][0] = Bh[(kp0 + lanek) * 136 + bcol];
                bb[ni][1] = Bh[(kp0 + 4 + lanek) * 136 + bcol];
            }
#pragma unroll
            for (int mi = 0; mi < 2; mi++)
#pragma unroll
                for (int ni = 0; ni < 8; ni++)
                    MMA_BF16(acc[mi][ni], ah[mi][0], ah[mi][1], ah[mi][2], ah[mi][3],
                             bb[ni][0], bb[ni][1]);
            // al x bh
#pragma unroll
            for (int mi = 0; mi < 2; mi++) {
                int base = (arow + mi * 16) * 20 + kp0 + lanek;
                al[mi][0] = Al[base];       al[mi][1] = Al[base + 160];
                al[mi][2] = Al[base + 4];   al[mi][3] = Al[base + 164];
            }
#pragma unroll
            for (int mi = 0; mi < 2; mi++)
#pragma unroll
                for (int ni = 0; ni < 8; ni++)
                    MMA_BF16(acc[mi][ni], al[mi][0], al[mi][1], al[mi][2], al[mi][3],
                             bb[ni][0], bb[ni][1]);
            // ah x bl (overwrite bb with lo weights)
#pragma unroll
            for (int ni = 0; ni < 8; ni++) {
                int bcol = warpN * 64 + ni * 8 + lane4;
                bb[ni][0] = Bl[(kp0 + lanek) * 136 + bcol];
                bb[ni][1] = Bl[(kp0 + 4 + lanek) * 136 + bcol];
            }
#pragma unroll
            for (int mi = 0; mi < 2; mi++)
#pragma unroll
                for (int ni = 0; ni < 8; ni++)
                    MMA_BF16(acc[mi][ni], ah[mi][0], ah[mi][1], ah[mi][2], ah[mi][3],
                             bb[ni][0], bb[ni][1]);
        }
    }

    // ---- epilogue: add bias, store ----
#pragma unroll
    for (int mi = 0; mi < 2; mi++) {
        int row = row0 + warpM * 32 + mi * 16 + lane4;
#pragma unroll
        for (int ni = 0; ni < 8; ni++) {
            int col = (nhalf << 7) + warpN * 64 + ni * 8 + lanek * 2;
            float2 bb2 = *reinterpret_cast<const float2*>(bias + col);
            float* d0 = y + (size_t)row * 256 + col;
            float* d1 = y + (size_t)(row + 8) * 256 + col;
            *reinterpret_cast<float2*>(d0) =
                make_float2(acc[mi][ni][0] + bb2.x, acc[mi][ni][1] + bb2.y);
            *reinterpret_cast<float2*>(d1) =
                make_float2(acc[mi][ni][2] + bb2.x, acc[mi][ni][3] + bb2.y);
        }
    }
}

// ================= dense GEMM (skip conv / classifier), FFMA2 core ==========
template <int N, int K, bool CONCAT>
__global__ __launch_bounds__(256, 2)
void dense_gemm(const float* __restrict__ a0, const float* __restrict__ a1,
                const float* __restrict__ wt, const float* __restrict__ bias,
                float* __restrict__ y)
{
    constexpr int TO = N / 32;
    constexpr int PT = TO / 2;
    __shared__ float2 Ash[64][19];
    __shared__ float  Wsh[16][N + 4];
    const int tid  = threadIdx.x;
    const int warp = tid >> 5;
    const int lane = tid & 31;
    const int row0 = blockIdx.x << 6;

    unsigned long long acc[8][PT];
#pragma unroll
    for (int i = 0; i < 8; i++)
#pragma unroll
        for (int j = 0; j < PT; j++) acc[i][j] = 0ull;

    const int gv  = tid >> 2;
    const int gc4 = (tid & 3) << 2;

    for (int k0 = 0; k0 < K; k0 += 16) {
        __syncthreads();
        const float* src;
        int koff, KS;
        if (CONCAT) {
            if (k0 < 256) { src = a0; koff = k0; }
            else          { src = a1; koff = k0 - 256; }
            KS = 256;
        } else {
            src = a0; koff = k0; KS = K;
        }
        {
            const float4 v = *reinterpret_cast<const float4*>(
                src + (size_t)(row0 + gv) * KS + koff + gc4);
            Ash[gv][gc4 + 0] = make_float2(v.x, v.x);
            Ash[gv][gc4 + 1] = make_float2(v.y, v.y);
            Ash[gv][gc4 + 2] = make_float2(v.z, v.z);
            Ash[gv][gc4 + 3] = make_float2(v.w, v.w);
        }
        {
            const float* wsrc = wt + (size_t)k0 * N;
            constexpr int NF4 = 16 * N / 4;
#pragma unroll
            for (int i = tid; i < NF4; i += 256) {
                int r  = i / (N / 4);
                int cc = (i % (N / 4)) << 2;
                *reinterpret_cast<float4*>(&Wsh[r][cc]) =
                    *reinterpret_cast<const float4*>(wsrc + r * N + cc);
            }
        }
        __syncthreads();
#pragma unroll
        for (int kk = 0; kk < 16; kk++) {
            unsigned long long a2[8];
#pragma unroll
            for (int i = 0; i < 8; i++)
                a2[i] = *reinterpret_cast<const unsigned long long*>(
                            &Ash[(warp << 3) + i][kk]);
            unsigned long long w2[PT];
            if (PT == 4) {
                ulonglong2 wA = *reinterpret_cast<const ulonglong2*>(&Wsh[kk][lane * 8]);
                ulonglong2 wB = *reinterpret_cast<const ulonglong2*>(&Wsh[kk][lane * 8 + 4]);
                w2[0] = wA.x; w2[1] = wA.y; w2[2] = wB.x; w2[3] = wB.y;
            } else if (PT == 2) {
                ulonglong2 wA = *reinterpret_cast<const ulonglong2*>(&Wsh[kk][lane * 4]);
                w2[0] = wA.x; w2[1] = wA.y;
            } else {
                w2[0] = *reinterpret_cast<const unsigned long long*>(&Wsh[kk][lane * 2]);
            }
#pragma unroll
            for (int i = 0; i < 8; i++)
#pragma unroll
                for (int j = 0; j < PT; j++)
                    FMA2(acc[i][j], a2[i], w2[j]);
        }
    }

    float bv[TO];
#pragma unroll
    for (int j = 0; j < TO; j++) bv[j] = bias[lane * TO + j];
#pragma unroll
    for (int i = 0; i < 8; i++) {
        int row = row0 + (warp << 3) + i;
#pragma unroll
        for (int j = 0; j < PT; j++) {
            float2 p = unpack2(acc[i][j]);
            y[(size_t)row * N + lane * TO + 2 * j]     = p.x + bv[2 * j];
            y[(size_t)row * N + lane * TO + 2 * j + 1] = p.y + bv[2 * j + 1];
        }
    }
}

// ---------------- encoder block 0 conv (C_in = 3, K = 36) ----------------
__global__ __launch_bounds__(256)
void enc0_conv(const float* __restrict__ verts, const int* __restrict__ idxp,
               const float* __restrict__ wt /*[m][o]*/, const float* __restrict__ bias,
               float* __restrict__ y)
{
    __shared__ float Wsh[36][256];
    __shared__ float A[8][36];
    __shared__ int   Js[12][128];
    const int tid  = threadIdx.x;
    const int row0 = blockIdx.x * 128;
    const int b    = row0 >> 14;
    const int u0   = row0 & (V_ - 1);
    const int baseB = b * V_;

    for (int i = tid; i < 36 * 256; i += 256) Wsh[i >> 8][i & 255] = wt[i];
    for (int i = tid; i < 12 * 128; i += 256) {
        int t = i >> 7, uu = i & 127;
        Js[t][uu] = idxp[t * V_ + u0 + uu];
    }
    const float bval = bias[tid];

    for (int g = 0; g < 16; g++) {
        __syncthreads();
        for (int i = tid; i < 8 * 36; i += 256) {
            int vv = i / 36, m = i % 36;
            int c = m / 12, t = m % 12;
            A[vv][m] = verts[(size_t)(baseB + Js[t][g * 8 + vv]) * 3 + c];
        }
        __syncthreads();
        float s[8];
#pragma unroll
        for (int v = 0; v < 8; v++) s[v] = bval;
#pragma unroll
        for (int m = 0; m < 36; m++) {
            float wm = Wsh[m][tid];
#pragma unroll
            for (int v = 0; v < 8; v++) s[v] = fmaf(wm, A[v][m], s[v]);
        }
#pragma unroll
        for (int v = 0; v < 8; v++)
            y[(size_t)(row0 + g * 8 + v) * 256 + tid] = s[v];
    }
}

// ---------------- BN stats (deterministic two-level reduction) ----------------
__global__ void stats_partial(const float* __restrict__ y, int C,
                              float* __restrict__ psum, float* __restrict__ psq)
{
    int tid = threadIdx.x;
    int r0  = blockIdx.x * 128;
    float s = 0.f, q = 0.f;
    for (int r = 0; r < 128; r++) {
        float v = y[(size_t)(r0 + r) * C + tid];
        s += v;
        q += v * v;
    }
    psum[blockIdx.x * C + tid] = s;
    psq [blockIdx.x * C + tid] = q;
}

__global__ void bn_finalize(const float* __restrict__ psum, const float* __restrict__ psq,
                            const float* __restrict__ g, const float* __restrict__ beta,
                            int C, float* __restrict__ scale, float* __restrict__ shift)
{
    __shared__ float ss[256];
    __shared__ float qq[256];
    int c = blockIdx.x;
    int i = threadIdx.x;
    ss[i] = psum[i * C + c];
    qq[i] = psq [i * C + c];
    __syncthreads();
#pragma unroll
    for (int s = 128; s > 0; s >>= 1) {
        if (i < s) { ss[i] += ss[i + s]; qq[i] += qq[i + s]; }
        __syncthreads();
    }
    if (i == 0) {
        float mean = ss[0] * (1.f / 32768.f);
        float var  = qq[0] * (1.f / 32768.f) - mean * mean;
        float sc   = g[c] * rsqrtf(var + 1e-5f);
        scale[c] = sc;
        shift[c] = beta[c] - mean * sc;
    }
}

__global__ void bn_apply(const float4* __restrict__ y, const float4* __restrict__ res,
                         float4* __restrict__ out, const float* __restrict__ scale,
                         const float* __restrict__ shift, int C4)
{
    int i  = blockIdx.x * 256 + threadIdx.x;
    int c4 = i & (C4 - 1);
    float4 sc = reinterpret_cast<const float4*>(scale)[c4];
    float4 sh = reinterpret_cast<const float4*>(shift)[c4];
    float4 v  = y[i];
    float4 r;
    r.x = fmaxf(fmaf(v.x, sc.x, sh.x), 0.f);
    r.y = fmaxf(fmaf(v.y, sc.y, sh.y), 0.f);
    r.z = fmaxf(fmaf(v.z, sc.z, sh.z), 0.f);
    r.w = fmaxf(fmaf(v.w, sc.w, sh.w), 0.f);
    if (res) {
        float4 rr = res[i];
        r.x += rr.x; r.y += rr.y; r.z += rr.z; r.w += rr.w;
    }
    out[i] = r;
}

// ---------------- SE ----------------
__global__ void se_partial(const float* __restrict__ z, float* __restrict__ sep)
{
    int tid = threadIdx.x;
    int r0  = blockIdx.x * 256;
    float s = 0.f;
    for (int r = 0; r < 256; r++) s += z[(size_t)(r0 + r) * 256 + tid];
    sep[blockIdx.x * 256 + tid] = s;
}

__global__ void se_gate(const float* __restrict__ sep, const float* __restrict__ w1,
                        const float* __restrict__ w2, float* __restrict__ gate)
{
    int tid = threadIdx.x;
    __shared__ float ss[256];
    __shared__ float hh[32];
    for (int b = 0; b < 2; b++) {
        float s = 0.f;
        for (int i = 0; i < 64; i++) s += sep[(b * 64 + i) * 256 + tid];
        ss[tid] = s * (1.f / 16384.f);
        __syncthreads();
        if (tid < 32) {
            float h = 0.f;
            for (int c = 0; c < 256; c++) h = fmaf(w1[tid * 256 + c], ss[c], h);
            hh[tid] = fmaxf(h, 0.f);
        }
        __syncthreads();
        float gs = 0.f;
#pragma unroll
        for (int r = 0; r < 32; r++) gs = fmaf(w2[tid * 32 + r], hh[r], gs);
        gate[b * 256 + tid] = 1.f / (1.f + expf(-gs));
        __syncthreads();
    }
}

__global__ void se_apply(const float4* __restrict__ z, const float* __restrict__ gate,
                         float4* __restrict__ out0, float4* __restrict__ out1)
{
    int i  = blockIdx.x * 256 + threadIdx.x;
    int c4 = i & 63;
    int b  = i >> 20;
    float4 g = reinterpret_cast<const float4*>(gate)[(b << 6) + c4];
    float4 v = z[i];
    float4 r = make_float4(v.x * g.x, v.y * g.y, v.z * g.z, v.w * g.w);
    out0[i] = r;
    if (out1) out1[i] = r;
}

// ---------------- classifier final 1x64 ----------------
__global__ void cls3_kernel(const float* __restrict__ h, const float* __restrict__ w,
                            const float* __restrict__ b, float* __restrict__ out)
{
    __shared__ float ws[64];
    int tid = threadIdx.x;
    if (tid < 64) ws[tid] = w[tid];
    __syncthreads();
    int bv = blockIdx.x * 256 + tid;
    const float4* hp = reinterpret_cast<const float4*>(h + (size_t)bv * 64);
    float s = __ldg(b);
#pragma unroll
    for (int i = 0; i < 16; i++) {
        float4 v = hp[i];
        s = fmaf(v.x, ws[i * 4 + 0], s);
        s = fmaf(v.y, ws[i * 4 + 1], s);
        s = fmaf(v.z, ws[i * 4 + 2], s);
        s = fmaf(v.w, ws[i * 4 + 3], s);
    }
    out[bv] = s;
}

// ---------------- host orchestration ----------------
extern "C" void kernel_launch(void* const* d_in, const int* in_sizes, int n_in,
                              void* d_out, int out_size)
{
    const float* verts   = (const float*)d_in[0];
    const int*   spirals = (const int*)  d_in[1];
    const float* enc0_w  = (const float*)d_in[2];
    const float* enc0_b  = (const float*)d_in[3];
    const float* enc0_g  = (const float*)d_in[4];
    const float* enc0_be = (const float*)d_in[5];
    const float* enc_w   = (const float*)d_in[6];
    const float* enc_b   = (const float*)d_in[7];
    const float* enc_g   = (const float*)d_in[8];
    const float* enc_be  = (const float*)d_in[9];
    const float* se_w1   = (const float*)d_in[10];
    const float* se_w2   = (const float*)d_in[11];
    const float* skip_w  = (const float*)d_in[12];
    const float* skip_b  = (const float*)d_in[13];
    const float* dec_w   = (const float*)d_in[14];
    const float* dec_b   = (const float*)d_in[15];
    const float* dec_g   = (const float*)d_in[16];
    const float* dec_be  = (const float*)d_in[17];
    const float* cls1_w  = (const float*)d_in[18];
    const float* cls1_b  = (const float*)d_in[19];
    const float* cls1_g  = (const float*)d_in[20];
    const float* cls1_be = (const float*)d_in[21];
    const float* cls2_w  = (const float*)d_in[22];
    const float* cls2_b  = (const float*)d_in[23];
    const float* cls2_g  = (const float*)d_in[24];
    const float* cls2_be = (const float*)d_in[25];
    const float* cls3_w  = (const float*)d_in[26];
    const float* cls3_b  = (const float*)d_in[27];
    float* outp = (float*)d_out;
    (void)in_sizes; (void)n_in; (void)out_size;

    float *px, *py, *pt, *pwt, *pps, *ppq, *psep, *psc, *psh, *pg;
    unsigned *pwbh, *pwbl;
    float *pf[3];
    cudaGetSymbolAddress((void**)&px,    g_x);
    cudaGetSymbolAddress((void**)&py,    g_y);
    cudaGetSymbolAddress((void**)&pt,    g_t);
    cudaGetSymbolAddress((void**)&pf[0], g_f0);
    cudaGetSymbolAddress((void**)&pf[1], g_f1);
    cudaGetSymbolAddress((void**)&pf[2], g_f2);
    cudaGetSymbolAddress((void**)&pwt,   g_wt);
    cudaGetSymbolAddress((void**)&pwbh,  g_wbh);
    cudaGetSymbolAddress((void**)&pwbl,  g_wbl);
    cudaGetSymbolAddress((void**)&pps,   g_psum);
    cudaGetSymbolAddress((void**)&ppq,   g_psq);
    cudaGetSymbolAddress((void**)&psep,  g_sep);
    cudaGetSymbolAddress((void**)&psc,   g_scale);
    cudaGetSymbolAddress((void**)&psh,   g_shift);
    cudaGetSymbolAddress((void**)&pg,    g_gate);

    // ---------- encoder block 0 ----------
    transpose_dense<<<(256 * 36 + 255) / 256, 256>>>(enc0_w, pwt, 256, 36);
    enc0_conv<<<256, 256>>>(verts, spirals, pwt, enc0_b, py);
    stats_partial<<<256, 256>>>(py, 256, pps, ppq);
    bn_finalize<<<256, 256>>>(pps, ppq, enc0_g, enc0_be, 256, psc, psh);
    bn_apply<<<8192, 256>>>((const float4*)py, nullptr, (float4*)pt, psc, psh, 64);
    se_partial<<<128, 256>>>(pt, psep);
    se_gate<<<1, 256>>>(psep, se_w1, se_w2, pg);
    se_apply<<<8192, 256>>>((const float4*)pt, pg, (float4*)px, (float4*)pf[0]);

    // ---------- encoder blocks 1..3 ----------
    for (int i = 1; i < 4; i++) {
        transpose_spiral_bf16<<<1536, 256>>>(enc_w + (size_t)(i - 1) * 786432, pwbh, pwbl);
        spiral_gemm_mma<<<512, 256>>>(px, spirals + i * (V_ * L_), pwbh, pwbl,
                                      enc_b + (i - 1) * 256, py);
        stats_partial<<<256, 256>>>(py, 256, pps, ppq);
        bn_finalize<<<256, 256>>>(pps, ppq, enc_g + (i - 1) * 256, enc_be + (i - 1) * 256,
                                  256, psc, psh);
        bn_apply<<<8192, 256>>>((const float4*)py, (const float4*)px, (float4*)pt,
                                psc, psh, 64);
        se_partial<<<128, 256>>>(pt, psep);
        se_gate<<<1, 256>>>(psep, se_w1 + i * 8192, se_w2 + i * 8192, pg);
        se_apply<<<8192, 256>>>((const float4*)pt, pg, (float4*)px,
                                (i < 3) ? (float4*)pf[i] : nullptr);
    }

    // ---------- decoder ----------
    for (int i = 0; i < 3; i++) {
        transpose_dense<<<(512 * 256 + 255) / 256, 256>>>(skip_w + (size_t)i * 131072,
                                                          pwt, 256, 512);
        dense_gemm<256, 512, true><<<512, 256>>>(px, pf[2 - i], pwt,
                                                 skip_b + i * 256, pt);
        transpose_spiral_bf16<<<1536, 256>>>(dec_w + (size_t)i * 786432, pwbh, pwbl);
        spiral_gemm_mma<<<512, 256>>>(pt, spirals + (2 - i) * (V_ * L_), pwbh, pwbl,
                                      dec_b + i * 256, py);
        stats_partial<<<256, 256>>>(py, 256, pps, ppq);
        bn_finalize<<<256, 256>>>(pps, ppq, dec_g + i * 256, dec_be + i * 256,
                                  256, psc, psh);
        bn_apply<<<8192, 256>>>((const float4*)py, (const float4*)pt, (float4*)px,
                                psc, psh, 64);
    }

    // ---------- classifier ----------
    transpose_dense<<<(128 * 256 + 255) / 256, 256>>>(cls1_w, pwt, 128, 256);
    dense_gemm<128, 256, false><<<512, 256>>>(px, nullptr, pwt, cls1_b, py);
    stats_partial<<<256, 128>>>(py, 128, pps, ppq);
    bn_finalize<<<128, 256>>>(pps, ppq, cls1_g, cls1_be, 128, psc, psh);
    bn_apply<<<4096, 256>>>((const float4*)py, nullptr, (float4*)pt, psc, psh, 32);

    transpose_dense<<<(64 * 128 + 255) / 256, 256>>>(cls2_w, pwt, 64, 128);
    dense_gemm<64, 128, false><<<512, 256>>>(pt, nullptr, pwt, cls2_b, py);
    stats_partial<<<256, 64>>>(py, 64, pps, ppq);
    bn_finalize<<<64, 256>>>(pps, ppq, cls2_g, cls2_be, 64, psc, psh);
    bn_apply<<<2048, 256>>>((const float4*)py, nullptr, (float4*)pt, psc, psh, 16);

    cls3_kernel<<<128, 256>>>(pt, cls3_w, cls3_b, outp);
}

// round 16
// speedup vs baseline: 1.1412x; 1.1407x over previous
#include <cuda_runtime.h>
#include <cuda_bf16.h>
#include <math.h>
#include <stdint.h>
#include <stddef.h>

#define V_  16384
#define BV_ 32768
#define C_  256
#define L_  12

// ---------------- packed helpers ----------------
#define FMA2(d, a, b) asm("fma.rn.f32x2 %0, %1, %2, %0;" : "+l"(d) : "l"(a), "l"(b))
__device__ __forceinline__ float2 unpack2(unsigned long long v) {
    float2 r;
    r.x = __uint_as_float((unsigned)(v & 0xffffffffu));
    r.y = __uint_as_float((unsigned)(v >> 32));
    return r;
}
// pack two floats to bf16x2 (first arg in low 16 bits)
__device__ __forceinline__ unsigned pack_bf2(float lo, float hi) {
    unsigned d;
    asm("cvt.rn.bf16x2.f32 %0, %1, %2;" : "=r"(d) : "f"(hi), "f"(lo));
    return d;
}
__device__ __forceinline__ float bf_round(float v) {
    return __bfloat162float(__float2bfloat16(v));
}

#define MMA_BF16(c, a0, a1, a2, a3, b0, b1) \
    asm volatile("mma.sync.aligned.m16n8k16.row.col.f32.bf16.bf16.f32 " \
        "{%0,%1,%2,%3}, {%4,%5,%6,%7}, {%8,%9}, {%0,%1,%2,%3};" \
        : "+f"((c)[0]), "+f"((c)[1]), "+f"((c)[2]), "+f"((c)[3]) \
        : "r"(a0), "r"(a1), "r"(a2), "r"(a3), "r"(b0), "r"(b1))

// ---------------- scratch (device globals; no allocations) ----------------
__device__ float g_x [BV_ * C_];
__device__ float g_y [BV_ * C_];
__device__ float g_t [BV_ * C_];
__device__ unsigned g_xh[BV_ * 128];
__device__ unsigned g_xl[BV_ * 128];
__device__ unsigned g_th[BV_ * 128];
__device__ unsigned g_tl[BV_ * 128];
__device__ unsigned g_fh0[BV_ * 128];
__device__ unsigned g_fl0[BV_ * 128];
__device__ unsigned g_fh1[BV_ * 128];
__device__ unsigned g_fl1[BV_ * 128];
__device__ unsigned g_fh2[BV_ * 128];
__device__ unsigned g_fl2[BV_ * 128];
__device__ float g_wt[16384];
__device__ unsigned g_wbh[96 * 16 * 256];   // spiral W packed hi [kc][kp][col]
__device__ unsigned g_wbl[96 * 16 * 256];
__device__ unsigned g_wdh[16 * 16 * 256];   // dense W packed hi  [kc][kp][col]
__device__ unsigned g_wdl[16 * 16 * 256];
__device__ float g_psum[256 * 256];
__device__ float g_psq [256 * 256];
__device__ float g_sep [128 * 256];
__device__ float g_scale[256];
__device__ float g_shift[256];
__device__ float g_gate[2 * 256];

// ================= weight preprocessing =====================================
// spiral weights w (256, 3072), m = c*12 + t.  k-order: k = t*256 + c.
__global__ void transpose_spiral_bf16(const float* __restrict__ w,
                                      unsigned* __restrict__ bh,
                                      unsigned* __restrict__ bl)
{
    int i   = blockIdx.x * 256 + threadIdx.x;   // 393216
    int col = i & 255;
    int kp  = (i >> 8) & 15;
    int kc  = i >> 12;
    int k0  = kc * 32 + kp * 2;
    float v0 = w[col * 3072 + (k0 & 255) * 12 + (k0 >> 8)];
    float v1 = w[col * 3072 + ((k0 + 1) & 255) * 12 + ((k0 + 1) >> 8)];
    float h0 = bf_round(v0), h1 = bf_round(v1);
    bh[i] = pack_bf2(h0, h1);
    bl[i] = pack_bf2(v0 - h0, v1 - h1);
}

// dense weights w (N, K) row-major -> packed [kc][kp][col], total (K/2)*N u32
__global__ void transpose_dense_bf16(const float* __restrict__ w,
                                     unsigned* __restrict__ bh,
                                     unsigned* __restrict__ bl, int N, int K)
{
    int i = blockIdx.x * 256 + threadIdx.x;
    if (i >= (K / 2) * N) return;
    int col = i % N;
    int r   = i / N;
    int kp  = r & 15;
    int kc  = r >> 4;
    int k0  = kc * 32 + kp * 2;
    float v0 = w[col * K + k0];
    float v1 = w[col * K + k0 + 1];
    float h0 = bf_round(v0), h1 = bf_round(v1);
    bh[i] = pack_bf2(h0, h1);
    bl[i] = pack_bf2(v0 - h0, v1 - h1);
}

// dense weights: w (N, K) -> wt[k*N + o]  (f32, for enc0/cls2)
__global__ void transpose_dense(const float* __restrict__ w, float* __restrict__ wt,
                                int N, int K)
{
    int i = blockIdx.x * 256 + threadIdx.x;
    if (i >= N * K) return;
    int o = i % N;
    int k = i / N;
    wt[i] = w[o * K + k];
}

// ================= spiral conv GEMM via mma.sync bf16x3 =====================
// A pre-split/packed: xh/xl rows of 128 u32 (bf16 pairs over 256 ch).
// CTA: 128 M x 128 N (grid = 256 Mblocks x 2 Nhalves). 8 warps of 32x64.
__global__ __launch_bounds__(256, 2)
void spiral_gemm_mma(const unsigned* __restrict__ xh, const unsigned* __restrict__ xl,
                     const int* __restrict__ idxp,
                     const unsigned* __restrict__ wbh, const unsigned* __restrict__ wbl,
                     const float* __restrict__ bias, float* __restrict__ y)
{
    __shared__ __align__(16) unsigned Ah[128 * 20];
    __shared__ __align__(16) unsigned Al[128 * 20];
    __shared__ __align__(16) unsigned Bh[16 * 136];
    __shared__ __align__(16) unsigned Bl[16 * 136];
    __shared__ int Js[12 * 128];

    const int tid   = threadIdx.x;
    const int wid   = tid >> 5;
    const int lane  = tid & 31;
    const int lane4 = lane >> 2;
    const int lanek = lane & 3;
    const int mb    = blockIdx.x >> 1;
    const int nhalf = blockIdx.x & 1;
    const int row0  = mb << 7;
    const int b     = row0 >> 14;
    const int u0    = row0 & (V_ - 1);
    const int baseB = b * V_;
    const int warpM = wid & 3;
    const int warpN = wid >> 2;

    for (int i = tid; i < 12 * 128; i += 256)
        Js[i] = idxp[(i >> 7) * V_ + u0 + (i & 127)];

    float acc[2][8][4];
#pragma unroll
    for (int mi = 0; mi < 2; mi++)
#pragma unroll
        for (int ni = 0; ni < 8; ni++)
#pragma unroll
            for (int j = 0; j < 4; j++) acc[mi][ni][j] = 0.f;

    const int arow = warpM * 32 + lane4;

    for (int kc = 0; kc < 96; kc++) {
        const int t    = kc >> 3;
        const int koff = (kc & 7) << 4;      // u32 offset within packed row
        __syncthreads();
        // ---- A tile: gather 128 rows x 16 u32 (hi + lo), pure copies ----
#pragma unroll
        for (int p = 0; p < 2; p++) {
            int f   = tid + (p << 8);        // 0..511
            int row = f >> 2;
            int kp0 = (f & 3) << 2;
            size_t src = ((size_t)(baseB + Js[(t << 7) + row]) << 7) + koff + kp0;
            *reinterpret_cast<uint4*>(&Ah[row * 20 + kp0]) =
                *reinterpret_cast<const uint4*>(xh + src);
            *reinterpret_cast<uint4*>(&Al[row * 20 + kp0]) =
                *reinterpret_cast<const uint4*>(xl + src);
        }
        // ---- B tiles: copy pre-packed weights (this CTA's 128-col half) ----
#pragma unroll
        for (int p = 0; p < 4; p++) {
            int f     = tid + (p << 8);      // 0..1023
            int split = f >> 9;
            int kp    = (f >> 5) & 15;
            int c4    = (f & 31) << 2;
            const unsigned* src = (split ? wbl : wbh)
                + ((size_t)(kc * 16 + kp) << 8) + (nhalf << 7) + c4;
            unsigned* dst = (split ? Bl : Bh) + kp * 136 + c4;
            *reinterpret_cast<uint4*>(dst) = *reinterpret_cast<const uint4*>(src);
        }
        __syncthreads();

#pragma unroll
        for (int ks = 0; ks < 2; ks++) {
            const int kp0 = ks << 3;
            unsigned ah[2][4], al[2][4], bb[8][2];
#pragma unroll
            for (int mi = 0; mi < 2; mi++) {
                int base = (arow + mi * 16) * 20 + kp0 + lanek;
                ah[mi][0] = Ah[base];       ah[mi][1] = Ah[base + 160];
                ah[mi][2] = Ah[base + 4];   ah[mi][3] = Ah[base + 164];
            }
#pragma unroll
            for (int ni = 0; ni < 8; ni++) {
                int bcol = warpN * 64 + ni * 8 + lane4;
                bb[ni][0] = Bh[(kp0 + lanek) * 136 + bcol];
                bb[ni][1] = Bh[(kp0 + 4 + lanek) * 136 + bcol];
            }
#pragma unroll
            for (int mi = 0; mi < 2; mi++)
#pragma unroll
                for (int ni = 0; ni < 8; ni++)
                    MMA_BF16(acc[mi][ni], ah[mi][0], ah[mi][1], ah[mi][2], ah[mi][3],
                             bb[ni][0], bb[ni][1]);
#pragma unroll
            for (int mi = 0; mi < 2; mi++) {
                int base = (arow + mi * 16) * 20 + kp0 + lanek;
                al[mi][0] = Al[base];       al[mi][1] = Al[base + 160];
                al[mi][2] = Al[base + 4];   al[mi][3] = Al[base + 164];
            }
#pragma unroll
            for (int mi = 0; mi < 2; mi++)
#pragma unroll
                for (int ni = 0; ni < 8; ni++)
                    MMA_BF16(acc[mi][ni], al[mi][0], al[mi][1], al[mi][2], al[mi][3],
                             bb[ni][0], bb[ni][1]);
#pragma unroll
            for (int ni = 0; ni < 8; ni++) {
                int bcol = warpN * 64 + ni * 8 + lane4;
                bb[ni][0] = Bl[(kp0 + lanek) * 136 + bcol];
                bb[ni][1] = Bl[(kp0 + 4 + lanek) * 136 + bcol];
            }
#pragma unroll
            for (int mi = 0; mi < 2; mi++)
#pragma unroll
                for (int ni = 0; ni < 8; ni++)
                    MMA_BF16(acc[mi][ni], ah[mi][0], ah[mi][1], ah[mi][2], ah[mi][3],
                             bb[ni][0], bb[ni][1]);
        }
    }

#pragma unroll
    for (int mi = 0; mi < 2; mi++) {
        int row = row0 + warpM * 32 + mi * 16 + lane4;
#pragma unroll
        for (int ni = 0; ni < 8; ni++) {
            int col = (nhalf << 7) + warpN * 64 + ni * 8 + lanek * 2;
            float2 bb2 = *reinterpret_cast<const float2*>(bias + col);
            float* d0 = y + (size_t)row * 256 + col;
            float* d1 = y + (size_t)(row + 8) * 256 + col;
            *reinterpret_cast<float2*>(d0) =
                make_float2(acc[mi][ni][0] + bb2.x, acc[mi][ni][1] + bb2.y);
            *reinterpret_cast<float2*>(d1) =
                make_float2(acc[mi][ni][2] + bb2.x, acc[mi][ni][3] + bb2.y);
        }
    }
}

// ================= dense GEMM via mma.sync bf16x3 ===========================
// A pre-split/packed (rows of 128 u32 = 256 ch). CONCAT: k<256 from a0, else a1.
template <int K, int NBLK, bool CONCAT, bool PACK>
__global__ __launch_bounds__(256, 2)
void dense_mma(const unsigned* __restrict__ a0h, const unsigned* __restrict__ a0l,
               const unsigned* __restrict__ a1h, const unsigned* __restrict__ a1l,
               const unsigned* __restrict__ wdh, const unsigned* __restrict__ wdl,
               const float* __restrict__ bias, float* __restrict__ y,
               unsigned* __restrict__ yh, unsigned* __restrict__ yl)
{
    constexpr int NTOT = NBLK * 128;
    constexpr int NKC  = K / 32;
    __shared__ __align__(16) unsigned Ah[128 * 20];
    __shared__ __align__(16) unsigned Al[128 * 20];
    __shared__ __align__(16) unsigned Bh[16 * 136];
    __shared__ __align__(16) unsigned Bl[16 * 136];

    const int tid   = threadIdx.x;
    const int wid   = tid >> 5;
    const int lane  = tid & 31;
    const int lane4 = lane >> 2;
    const int lanek = lane & 3;
    const int mb    = (NBLK == 2) ? (blockIdx.x >> 1) : blockIdx.x;
    const int nhalf = (NBLK == 2) ? (blockIdx.x & 1) : 0;
    const int row0  = mb << 7;
    const int warpM = wid & 3;
    const int warpN = wid >> 2;

    float acc[2][8][4];
#pragma unroll
    for (int mi = 0; mi < 2; mi++)
#pragma unroll
        for (int ni = 0; ni < 8; ni++)
#pragma unroll
            for (int j = 0; j < 4; j++) acc[mi][ni][j] = 0.f;

    const int arow = warpM * 32 + lane4;

    for (int kc = 0; kc < NKC; kc++) {
        __syncthreads();
        const unsigned* sh;
        const unsigned* sl;
        int koff;
        if (CONCAT && kc >= 8) { sh = a1h; sl = a1l; koff = (kc - 8) << 4; }
        else                   { sh = a0h; sl = a0l; koff = kc << 4; }
#pragma unroll
        for (int p = 0; p < 2; p++) {
            int f   = tid + (p << 8);
            int row = f >> 2;
            int kp0 = (f & 3) << 2;
            size_t src = ((size_t)(row0 + row) << 7) + koff + kp0;
            *reinterpret_cast<uint4*>(&Ah[row * 20 + kp0]) =
                *reinterpret_cast<const uint4*>(sh + src);
            *reinterpret_cast<uint4*>(&Al[row * 20 + kp0]) =
                *reinterpret_cast<const uint4*>(sl + src);
        }
#pragma unroll
        for (int p = 0; p < 4; p++) {
            int f     = tid + (p << 8);
            int split = f >> 9;
            int kp    = (f >> 5) & 15;
            int c4    = (f & 31) << 2;
            const unsigned* src = (split ? wdl : wdh)
                + (size_t)(kc * 16 + kp) * NTOT + (nhalf << 7) + c4;
            unsigned* dst = (split ? Bl : Bh) + kp * 136 + c4;
            *reinterpret_cast<uint4*>(dst) = *reinterpret_cast<const uint4*>(src);
        }
        __syncthreads();

#pragma unroll
        for (int ks = 0; ks < 2; ks++) {
            const int kp0 = ks << 3;
            unsigned ah[2][4], al[2][4], bb[8][2];
#pragma unroll
            for (int mi = 0; mi < 2; mi++) {
                int base = (arow + mi * 16) * 20 + kp0 + lanek;
                ah[mi][0] = Ah[base];       ah[mi][1] = Ah[base + 160];
                ah[mi][2] = Ah[base + 4];   ah[mi][3] = Ah[base + 164];
            }
#pragma unroll
            for (int ni = 0; ni < 8; ni++) {
                int bcol = warpN * 64 + ni * 8 + lane4;
                bb[ni][0] = Bh[(kp0 + lanek) * 136 + bcol];
                bb[ni][1] = Bh[(kp0 + 4 + lanek) * 136 + bcol];
            }
#pragma unroll
            for (int mi = 0; mi < 2; mi++)
#pragma unroll
                for (int ni = 0; ni < 8; ni++)
                    MMA_BF16(acc[mi][ni], ah[mi][0], ah[mi][1], ah[mi][2], ah[mi][3],
                             bb[ni][0], bb[ni][1]);
#pragma unroll
            for (int mi = 0; mi < 2; mi++) {
                int base = (arow + mi * 16) * 20 + kp0 + lanek;
                al[mi][0] = Al[base];       al[mi][1] = Al[base + 160];
                al[mi][2] = Al[base + 4];   al[mi][3] = Al[base + 164];
            }
#pragma unroll
            for (int mi = 0; mi < 2; mi++)
#pragma unroll
                for (int ni = 0; ni < 8; ni++)
                    MMA_BF16(acc[mi][ni], al[mi][0], al[mi][1], al[mi][2], al[mi][3],
                             bb[ni][0], bb[ni][1]);
#pragma unroll
            for (int ni = 0; ni < 8; ni++) {
                int bcol = warpN * 64 + ni * 8 + lane4;
                bb[ni][0] = Bl[(kp0 + lanek) * 136 + bcol];
                bb[ni][1] = Bl[(kp0 + 4 + lanek) * 136 + bcol];
            }
#pragma unroll
            for (int mi = 0; mi < 2; mi++)
#pragma unroll
                for (int ni = 0; ni < 8; ni++)
                    MMA_BF16(acc[mi][ni], ah[mi][0], ah[mi][1], ah[mi][2], ah[mi][3],
                             bb[ni][0], bb[ni][1]);
        }
    }

#pragma unroll
    for (int mi = 0; mi < 2; mi++) {
        int row = row0 + warpM * 32 + mi * 16 + lane4;
#pragma unroll
        for (int ni = 0; ni < 8; ni++) {
            int col = (nhalf << 7) + warpN * 64 + ni * 8 + lanek * 2;
            float2 bb2 = *reinterpret_cast<const float2*>(bias + col);
            float v0 = acc[mi][ni][0] + bb2.x;
            float v1 = acc[mi][ni][1] + bb2.y;
            float v2 = acc[mi][ni][2] + bb2.x;
            float v3 = acc[mi][ni][3] + bb2.y;
            *reinterpret_cast<float2*>(y + (size_t)row * NTOT + col) = make_float2(v0, v1);
            *reinterpret_cast<float2*>(y + (size_t)(row + 8) * NTOT + col) = make_float2(v2, v3);
            if (PACK) {
                float h0 = bf_round(v0), h1 = bf_round(v1);
                float h2 = bf_round(v2), h3 = bf_round(v3);
                yh[(size_t)row * 128 + (col >> 1)]       = pack_bf2(h0, h1);
                yl[(size_t)row * 128 + (col >> 1)]       = pack_bf2(v0 - h0, v1 - h1);
                yh[(size_t)(row + 8) * 128 + (col >> 1)] = pack_bf2(h2, h3);
                yl[(size_t)(row + 8) * 128 + (col >> 1)] = pack_bf2(v2 - h2, v3 - h3);
            }
        }
    }
}

// ================= dense GEMM FFMA2 (cls2 only) =============================
template <int N, int K>
__global__ __launch_bounds__(256, 2)
void dense_gemm(const float* __restrict__ a0, const float* __restrict__ wt,
                const float* __restrict__ bias, float* __restrict__ y)
{
    constexpr int TO = N / 32;
    constexpr int PT = TO / 2;
    __shared__ float2 Ash[64][19];
    __shared__ float  Wsh[16][N + 4];
    const int tid  = threadIdx.x;
    const int warp = tid >> 5;
    const int lane = tid & 31;
    const int row0 = blockIdx.x << 6;

    unsigned long long acc[8][PT];
#pragma unroll
    for (int i = 0; i < 8; i++)
#pragma unroll
        for (int j = 0; j < PT; j++) acc[i][j] = 0ull;

    const int gv  = tid >> 2;
    const int gc4 = (tid & 3) << 2;

    for (int k0 = 0; k0 < K; k0 += 16) {
        __syncthreads();
        {
            const float4 v = *reinterpret_cast<const float4*>(
                a0 + (size_t)(row0 + gv) * K + k0 + gc4);
            Ash[gv][gc4 + 0] = make_float2(v.x, v.x);
            Ash[gv][gc4 + 1] = make_float2(v.y, v.y);
            Ash[gv][gc4 + 2] = make_float2(v.z, v.z);
            Ash[gv][gc4 + 3] = make_float2(v.w, v.w);
        }
        {
            const float* wsrc = wt + (size_t)k0 * N;
            constexpr int NF4 = 16 * N / 4;
#pragma unroll
            for (int i = tid; i < NF4; i += 256) {
                int r  = i / (N / 4);
                int cc = (i % (N / 4)) << 2;
                *reinterpret_cast<float4*>(&Wsh[r][cc]) =
                    *reinterpret_cast<const float4*>(wsrc + r * N + cc);
            }
        }
        __syncthreads();
#pragma unroll
        for (int kk = 0; kk < 16; kk++) {
            unsigned long long a2[8];
#pragma unroll
            for (int i = 0; i < 8; i++)
                a2[i] = *reinterpret_cast<const unsigned long long*>(
                            &Ash[(warp << 3) + i][kk]);
            unsigned long long w2[PT];
            if (PT == 2) {
                ulonglong2 wA = *reinterpret_cast<const ulonglong2*>(&Wsh[kk][lane * 4]);
                w2[0] = wA.x; w2[1] = wA.y;
            } else {
                w2[0] = *reinterpret_cast<const unsigned long long*>(&Wsh[kk][lane * 2]);
            }
#pragma unroll
            for (int i = 0; i < 8; i++)
#pragma unroll
                for (int j = 0; j < PT; j++)
                    FMA2(acc[i][j], a2[i], w2[j]);
        }
    }

    float bv[TO];
#pragma unroll
    for (int j = 0; j < TO; j++) bv[j] = bias[lane * TO + j];
#pragma unroll
    for (int i = 0; i < 8; i++) {
        int row = row0 + (warp << 3) + i;
#pragma unroll
        for (int j = 0; j < PT; j++) {
            float2 p = unpack2(acc[i][j]);
            y[(size_t)row * N + lane * TO + 2 * j]     = p.x + bv[2 * j];
            y[(size_t)row * N + lane * TO + 2 * j + 1] = p.y + bv[2 * j + 1];
        }
    }
}

// ---------------- encoder block 0 conv (C_in = 3, K = 36) ----------------
__global__ __launch_bounds__(256)
void enc0_conv(const float* __restrict__ verts, const int* __restrict__ idxp,
               const float* __restrict__ wt, const float* __restrict__ bias,
               float* __restrict__ y)
{
    __shared__ float Wsh[36][256];
    __shared__ float A[8][36];
    __shared__ int   Js[12][128];
    const int tid  = threadIdx.x;
    const int row0 = blockIdx.x * 128;
    const int b    = row0 >> 14;
    const int u0   = row0 & (V_ - 1);
    const int baseB = b * V_;

    for (int i = tid; i < 36 * 256; i += 256) Wsh[i >> 8][i & 255] = wt[i];
    for (int i = tid; i < 12 * 128; i += 256) {
        int t = i >> 7, uu = i & 127;
        Js[t][uu] = idxp[t * V_ + u0 + uu];
    }
    const float bval = bias[tid];

    for (int g = 0; g < 16; g++) {
        __syncthreads();
        for (int i = tid; i < 8 * 36; i += 256) {
            int vv = i / 36, m = i % 36;
            int c = m / 12, t = m % 12;
            A[vv][m] = verts[(size_t)(baseB + Js[t][g * 8 + vv]) * 3 + c];
        }
        __syncthreads();
        float s[8];
#pragma unroll
        for (int v = 0; v < 8; v++) s[v] = bval;
#pragma unroll
        for (int m = 0; m < 36; m++) {
            float wm = Wsh[m][tid];
#pragma unroll
            for (int v = 0; v < 8; v++) s[v] = fmaf(wm, A[v][m], s[v]);
        }
#pragma unroll
        for (int v = 0; v < 8; v++)
            y[(size_t)(row0 + g * 8 + v) * 256 + tid] = s[v];
    }
}

// ---------------- BN stats ----------------
__global__ void stats_partial(const float* __restrict__ y, int C,
                              float* __restrict__ psum, float* __restrict__ psq)
{
    int tid = threadIdx.x;
    int r0  = blockIdx.x * 128;
    float s = 0.f, q = 0.f;
    for (int r = 0; r < 128; r++) {
        float v = y[(size_t)(r0 + r) * C + tid];
        s += v;
        q += v * v;
    }
    psum[blockIdx.x * C + tid] = s;
    psq [blockIdx.x * C + tid] = q;
}

__global__ void bn_finalize(const float* __restrict__ psum, const float* __restrict__ psq,
                            const float* __restrict__ g, const float* __restrict__ beta,
                            int C, float* __restrict__ scale, float* __restrict__ shift)
{
    __shared__ float ss[256];
    __shared__ float qq[256];
    int c = blockIdx.x;
    int i = threadIdx.x;
    ss[i] = psum[i * C + c];
    qq[i] = psq [i * C + c];
    __syncthreads();
#pragma unroll
    for (int s = 128; s > 0; s >>= 1) {
        if (i < s) { ss[i] += ss[i + s]; qq[i] += qq[i + s]; }
        __syncthreads();
    }
    if (i == 0) {
        float mean = ss[0] * (1.f / 32768.f);
        float var  = qq[0] * (1.f / 32768.f) - mean * mean;
        float sc   = g[c] * rsqrtf(var + 1e-5f);
        scale[c] = sc;
        shift[c] = beta[c] - mean * sc;
    }
}

// out = relu(y*scale + shift) [+ res]; optionally emit packed bf16 hi/lo
__global__ void bn_apply(const float4* __restrict__ y, const float4* __restrict__ res,
                         float4* __restrict__ out,
                         unsigned* __restrict__ outh, unsigned* __restrict__ outl,
                         const float* __restrict__ scale,
                         const float* __restrict__ shift, int C4)
{
    int i  = blockIdx.x * 256 + threadIdx.x;
    int c4 = i & (C4 - 1);
    float4 sc = reinterpret_cast<const float4*>(scale)[c4];
    float4 sh = reinterpret_cast<const float4*>(shift)[c4];
    float4 v  = y[i];
    float4 r;
    r.x = fmaxf(fmaf(v.x, sc.x, sh.x), 0.f);
    r.y = fmaxf(fmaf(v.y, sc.y, sh.y), 0.f);
    r.z = fmaxf(fmaf(v.z, sc.z, sh.z), 0.f);
    r.w = fmaxf(fmaf(v.w, sc.w, sh.w), 0.f);
    if (res) {
        float4 rr = res[i];
        r.x += rr.x; r.y += rr.y; r.z += rr.z; r.w += rr.w;
    }
    out[i] = r;
    if (outh) {
        float hx = bf_round(r.x), hy = bf_round(r.y);
        float hz = bf_round(r.z), hw = bf_round(r.w);
        outh[i * 2]     = pack_bf2(hx, hy);
        outh[i * 2 + 1] = pack_bf2(hz, hw);
        outl[i * 2]     = pack_bf2(r.x - hx, r.y - hy);
        outl[i * 2 + 1] = pack_bf2(r.z - hz, r.w - hw);
    }
}

// ---------------- SE ----------------
__global__ void se_partial(const float* __restrict__ z, float* __restrict__ sep)
{
    int tid = threadIdx.x;
    int r0  = blockIdx.x * 256;
    float s = 0.f;
    for (int r = 0; r < 256; r++) s += z[(size_t)(r0 + r) * 256 + tid];
    sep[blockIdx.x * 256 + tid] = s;
}

__global__ void se_gate(const float* __restrict__ sep, const float* __restrict__ w1,
                        const float* __restrict__ w2, float* __restrict__ gate)
{
    int tid = threadIdx.x;
    __shared__ float ss[256];
    __shared__ float hh[32];
    for (int b = 0; b < 2; b++) {
        float s = 0.f;
        for (int i = 0; i < 64; i++) s += sep[(b * 64 + i) * 256 + tid];
        ss[tid] = s * (1.f / 16384.f);
        __syncthreads();
        if (tid < 32) {
            float h = 0.f;
            for (int c = 0; c < 256; c++) h = fmaf(w1[tid * 256 + c], ss[c], h);
            hh[tid] = fmaxf(h, 0.f);
        }
        __syncthreads();
        float gs = 0.f;
#pragma unroll
        for (int r = 0; r < 32; r++) gs = fmaf(w2[tid * 32 + r], hh[r], gs);
        gate[b * 256 + tid] = 1.f / (1.f + expf(-gs));
        __syncthreads();
    }
}

// writes f32 out0, packed out (oh/ol), and optionally packed feat copy (fh/fl)
__global__ void se_apply(const float4* __restrict__ z, const float* __restrict__ gate,
                         float4* __restrict__ out0,
                         unsigned* __restrict__ oh, unsigned* __restrict__ ol,
                         unsigned* __restrict__ fh, unsigned* __restrict__ fl)
{
    int i  = blockIdx.x * 256 + threadIdx.x;
    int c4 = i & 63;
    int b  = i >> 20;
    float4 g = reinterpret_cast<const float4*>(gate)[(b << 6) + c4];
    float4 v = z[i];
    float4 r = make_float4(v.x * g.x, v.y * g.y, v.z * g.z, v.w * g.w);
    out0[i] = r;
    float hx = bf_round(r.x), hy = bf_round(r.y);
    float hz = bf_round(r.z), hw = bf_round(r.w);
    unsigned h0 = pack_bf2(hx, hy), h1 = pack_bf2(hz, hw);
    unsigned l0 = pack_bf2(r.x - hx, r.y - hy), l1 = pack_bf2(r.z - hz, r.w - hw);
    oh[i * 2] = h0; oh[i * 2 + 1] = h1;
    ol[i * 2] = l0; ol[i * 2 + 1] = l1;
    if (fh) {
        fh[i * 2] = h0; fh[i * 2 + 1] = h1;
        fl[i * 2] = l0; fl[i * 2 + 1] = l1;
    }
}

// ---------------- classifier final 1x64 ----------------
__global__ void cls3_kernel(const float* __restrict__ h, const float* __restrict__ w,
                            const float* __restrict__ b, float* __restrict__ out)
{
    __shared__ float ws[64];
    int tid = threadIdx.x;
    if (tid < 64) ws[tid] = w[tid];
    __syncthreads();
    int bv = blockIdx.x * 256 + tid;
    const float4* hp = reinterpret_cast<const float4*>(h + (size_t)bv * 64);
    float s = __ldg(b);
#pragma unroll
    for (int i = 0; i < 16; i++) {
        float4 v = hp[i];
        s = fmaf(v.x, ws[i * 4 + 0], s);
        s = fmaf(v.y, ws[i * 4 + 1], s);
        s = fmaf(v.z, ws[i * 4 + 2], s);
        s = fmaf(v.w, ws[i * 4 + 3], s);
    }
    out[bv] = s;
}

// ---------------- host orchestration ----------------
extern "C" void kernel_launch(void* const* d_in, const int* in_sizes, int n_in,
                              void* d_out, int out_size)
{
    const float* verts   = (const float*)d_in[0];
    const int*   spirals = (const int*)  d_in[1];
    const float* enc0_w  = (const float*)d_in[2];
    const float* enc0_b  = (const float*)d_in[3];
    const float* enc0_g  = (const float*)d_in[4];
    const float* enc0_be = (const float*)d_in[5];
    const float* enc_w   = (const float*)d_in[6];
    const float* enc_b   = (const float*)d_in[7];
    const float* enc_g   = (const float*)d_in[8];
    const float* enc_be  = (const float*)d_in[9];
    const float* se_w1   = (const float*)d_in[10];
    const float* se_w2   = (const float*)d_in[11];
    const float* skip_w  = (const float*)d_in[12];
    const float* skip_b  = (const float*)d_in[13];
    const float* dec_w   = (const float*)d_in[14];
    const float* dec_b   = (const float*)d_in[15];
    const float* dec_g   = (const float*)d_in[16];
    const float* dec_be  = (const float*)d_in[17];
    const float* cls1_w  = (const float*)d_in[18];
    const float* cls1_b  = (const float*)d_in[19];
    const float* cls1_g  = (const float*)d_in[20];
    const float* cls1_be = (const float*)d_in[21];
    const float* cls2_w  = (const float*)d_in[22];
    const float* cls2_b  = (const float*)d_in[23];
    const float* cls2_g  = (const float*)d_in[24];
    const float* cls2_be = (const float*)d_in[25];
    const float* cls3_w  = (const float*)d_in[26];
    const float* cls3_b  = (const float*)d_in[27];
    float* outp = (float*)d_out;
    (void)in_sizes; (void)n_in; (void)out_size;

    float *px, *py, *pt, *pwt, *pps, *ppq, *psep, *psc, *psh, *pg;
    unsigned *pxh, *pxl, *pth, *ptl, *pwbh, *pwbl, *pwdh, *pwdl;
    unsigned *pfh[3], *pfl[3];
    cudaGetSymbolAddress((void**)&px,     g_x);
    cudaGetSymbolAddress((void**)&py,     g_y);
    cudaGetSymbolAddress((void**)&pt,     g_t);
    cudaGetSymbolAddress((void**)&pxh,    g_xh);
    cudaGetSymbolAddress((void**)&pxl,    g_xl);
    cudaGetSymbolAddress((void**)&pth,    g_th);
    cudaGetSymbolAddress((void**)&ptl,    g_tl);
    cudaGetSymbolAddress((void**)&pfh[0], g_fh0);
    cudaGetSymbolAddress((void**)&pfl[0], g_fl0);
    cudaGetSymbolAddress((void**)&pfh[1], g_fh1);
    cudaGetSymbolAddress((void**)&pfl[1], g_fl1);
    cudaGetSymbolAddress((void**)&pfh[2], g_fh2);
    cudaGetSymbolAddress((void**)&pfl[2], g_fl2);
    cudaGetSymbolAddress((void**)&pwt,    g_wt);
    cudaGetSymbolAddress((void**)&pwbh,   g_wbh);
    cudaGetSymbolAddress((void**)&pwbl,   g_wbl);
    cudaGetSymbolAddress((void**)&pwdh,   g_wdh);
    cudaGetSymbolAddress((void**)&pwdl,   g_wdl);
    cudaGetSymbolAddress((void**)&pps,    g_psum);
    cudaGetSymbolAddress((void**)&ppq,    g_psq);
    cudaGetSymbolAddress((void**)&psep,   g_sep);
    cudaGetSymbolAddress((void**)&psc,    g_scale);
    cudaGetSymbolAddress((void**)&psh,    g_shift);
    cudaGetSymbolAddress((void**)&pg,     g_gate);

    // ---------- encoder block 0 ----------
    transpose_dense<<<(256 * 36 + 255) / 256, 256>>>(enc0_w, pwt, 256, 36);
    enc0_conv<<<256, 256>>>(verts, spirals, pwt, enc0_b, py);
    stats_partial<<<256, 256>>>(py, 256, pps, ppq);
    bn_finalize<<<256, 256>>>(pps, ppq, enc0_g, enc0_be, 256, psc, psh);
    bn_apply<<<8192, 256>>>((const float4*)py, nullptr, (float4*)pt,
                            nullptr, nullptr, psc, psh, 64);
    se_partial<<<128, 256>>>(pt, psep);
    se_gate<<<1, 256>>>(psep, se_w1, se_w2, pg);
    se_apply<<<8192, 256>>>((const float4*)pt, pg, (float4*)px,
                            pxh, pxl, pfh[0], pfl[0]);

    // ---------- encoder blocks 1..3 ----------
    for (int i = 1; i < 4; i++) {
        transpose_spiral_bf16<<<1536, 256>>>(enc_w + (size_t)(i - 1) * 786432, pwbh, pwbl);
        spiral_gemm_mma<<<512, 256>>>(pxh, pxl, spirals + i * (V_ * L_), pwbh, pwbl,
                                      enc_b + (i - 1) * 256, py);
        stats_partial<<<256, 256>>>(py, 256, pps, ppq);
        bn_finalize<<<256, 256>>>(pps, ppq, enc_g + (i - 1) * 256, enc_be + (i - 1) * 256,
                                  256, psc, psh);
        bn_apply<<<8192, 256>>>((const float4*)py, (const float4*)px, (float4*)pt,
                                nullptr, nullptr, psc, psh, 64);
        se_partial<<<128, 256>>>(pt, psep);
        se_gate<<<1, 256>>>(psep, se_w1 + i * 8192, se_w2 + i * 8192, pg);
        se_apply<<<8192, 256>>>((const float4*)pt, pg, (float4*)px, pxh, pxl,
                                (i < 3) ? pfh[i] : nullptr,
                                (i < 3) ? pfl[i] : nullptr);
    }

    // ---------- decoder ----------
    for (int i = 0; i < 3; i++) {
        transpose_dense_bf16<<<256, 256>>>(skip_w + (size_t)i * 131072, pwdh, pwdl,
                                           256, 512);
        dense_mma<512, 2, true, true><<<512, 256>>>(pxh, pxl, pfh[2 - i], pfl[2 - i],
                                                    pwdh, pwdl, skip_b + i * 256,
                                                    pt, pth, ptl);
        transpose_spiral_bf16<<<1536, 256>>>(dec_w + (size_t)i * 786432, pwbh, pwbl);
        spiral_gemm_mma<<<512, 256>>>(pth, ptl, spirals + (2 - i) * (V_ * L_), pwbh, pwbl,
                                      dec_b + i * 256, py);
        stats_partial<<<256, 256>>>(py, 256, pps, ppq);
        bn_finalize<<<256, 256>>>(pps, ppq, dec_g + i * 256, dec_be + i * 256,
                                  256, psc, psh);
        bn_apply<<<8192, 256>>>((const float4*)py, (const float4*)pt, (float4*)px,
                                pxh, pxl, psc, psh, 64);
    }

    // ---------- classifier ----------
    transpose_dense_bf16<<<64, 256>>>(cls1_w, pwdh, pwdl, 128, 256);
    dense_mma<256, 1, false, false><<<256, 256>>>(pxh, pxl, nullptr, nullptr,
                                                  pwdh, pwdl, cls1_b, py,
                                                  nullptr, nullptr);
    stats_partial<<<256, 128>>>(py, 128, pps, ppq);
    bn_finalize<<<128, 256>>>(pps, ppq, cls1_g, cls1_be, 128, psc, psh);
    bn_apply<<<4096, 256>>>((const float4*)py, nullptr, (float4*)pt,
                            nullptr, nullptr, psc, psh, 32);

    transpose_dense<<<(64 * 128 + 255) / 256, 256>>>(cls2_w, pwt, 64, 128);
    dense_gemm<64, 128><<<512, 256>>>(pt, pwt, cls2_b, py);
    stats_partial<<<256, 64>>>(py, 64, pps, ppq);
    bn_finalize<<<64, 256>>>(pps, ppq, cls2_g, cls2_be, 64, psc, psh);
    bn_apply<<<2048, 256>>>((const float4*)py, nullptr, (float4*)pt,
                            nullptr, nullptr, psc, psh, 16);

    cls3_kernel<<<128, 256>>>(pt, cls3_w, cls3_b, outp);
}